// round 13
// baseline (speedup 1.0000x reference)
#include <cuda_runtime.h>
#include <cuda_bf16.h>
#include <cuda_fp16.h>
#include <math.h>
#include <stdint.h>

#define EMB 1024
#define HID 4096
#define NH 16
#define DKH 64
#define BATCH 2
#define SEQ 2048
#define MROWS (BATCH * SEQ)     // 4096
#define QKVW (3 * EMB)

// ---------------- scratch (__device__ globals, allocation-free) ---------------
__device__ __nv_bfloat16 g_ab  [MROWS * EMB];            // ln1 out, later attn out
__device__ uint16_t      g_xh  [MROWS * EMB];            // ln2 out (fp16)
__device__ uint16_t      g_ffh [(size_t)MROWS * HID];    // relu(ff1) (fp16)
__device__ uint16_t      g_wh  [(size_t)2 * HID * EMB];  // fp16 transposed ff1 | ff2
__device__ __nv_bfloat16 g_wp  [(size_t)(4 * EMB) * EMB];// plain transposed qkv|wo
__device__ __nv_bfloat16 g_qkvh[(size_t)MROWS * QKVW];   // packed q|k|v bf16
__device__ float g_h   [MROWS * EMB];
__device__ float g_part[(size_t)4 * MROWS * EMB];        // split-K partials

// ---------------- PTX helpers (base ISA only) ----------------------------------
__device__ __forceinline__ uint32_t smem_u32(const void* p) {
    return (uint32_t)__cvta_generic_to_shared(p);
}
__device__ __forceinline__ void cp16(uint32_t dst, const void* src) {
    asm volatile("cp.async.cg.shared.global [%0], [%1], 16;" :: "r"(dst), "l"(src));
}
__device__ __forceinline__ void cp_commit() {
    asm volatile("cp.async.commit_group;");
}
template<int N> __device__ __forceinline__ void cp_wait() {
    asm volatile("cp.async.wait_group %0;" :: "n"(N));
}
__device__ __forceinline__ void ldsm_x4(uint32_t* r, uint32_t addr) {
    asm volatile("ldmatrix.sync.aligned.m8n8.x4.shared.b16 {%0,%1,%2,%3}, [%4];"
                 : "=r"(r[0]), "=r"(r[1]), "=r"(r[2]), "=r"(r[3]) : "r"(addr));
}
__device__ __forceinline__ void ldsm_x4t(uint32_t* r, uint32_t addr) {
    asm volatile("ldmatrix.sync.aligned.m8n8.x4.trans.shared.b16 {%0,%1,%2,%3}, [%4];"
                 : "=r"(r[0]), "=r"(r[1]), "=r"(r[2]), "=r"(r[3]) : "r"(addr));
}
template<int FP16>
__device__ __forceinline__ void mma16(float* d, const uint32_t* a, const uint32_t* b) {
    if (FP16)
        asm volatile(
            "mma.sync.aligned.m16n8k16.row.col.f32.f16.f16.f32 "
            "{%0,%1,%2,%3}, {%4,%5,%6,%7}, {%8,%9}, {%0,%1,%2,%3};"
            : "+f"(d[0]), "+f"(d[1]), "+f"(d[2]), "+f"(d[3])
            : "r"(a[0]), "r"(a[1]), "r"(a[2]), "r"(a[3]), "r"(b[0]), "r"(b[1]));
    else
        asm volatile(
            "mma.sync.aligned.m16n8k16.row.col.f32.bf16.bf16.f32 "
            "{%0,%1,%2,%3}, {%4,%5,%6,%7}, {%8,%9}, {%0,%1,%2,%3};"
            : "+f"(d[0]), "+f"(d[1]), "+f"(d[2]), "+f"(d[3])
            : "r"(a[0]), "r"(a[1]), "r"(a[2]), "r"(a[3]), "r"(b[0]), "r"(b[1]));
}
template<int FP16>
__device__ __forceinline__ uint32_t pack2(float a, float b) {
    if (FP16) { __half2 h = __floats2half2_rn(a, b); return *(uint32_t*)&h; }
    __nv_bfloat162 h = __floats2bfloat162_rn(a, b); return *(uint32_t*)&h;
}
__device__ __forceinline__ uint32_t packbf(float a, float b) {
    __nv_bfloat162 h = __floats2bfloat162_rn(a, b);
    return *(uint32_t*)&h;
}

// ---------------- LayerNorm ----------------------------------------------------
__device__ __forceinline__ void ln_stats(float4 v, float& mean, float& inv,
                                         const float* al) {
    float s  = v.x + v.y + v.z + v.w;
    float ss = v.x*v.x + v.y*v.y + v.z*v.z + v.w*v.w;
    #pragma unroll
    for (int off = 16; off; off >>= 1) {
        s  += __shfl_xor_sync(0xffffffffu, s,  off);
        ss += __shfl_xor_sync(0xffffffffu, ss, off);
    }
    __shared__ float rs[8], rss[8];
    int warp = threadIdx.x >> 5, lane = threadIdx.x & 31;
    if (lane == 0) { rs[warp] = s; rss[warp] = ss; }
    __syncthreads();
    if (warp == 0) {
        s  = (lane < 8) ? rs[lane]  : 0.f;
        ss = (lane < 8) ? rss[lane] : 0.f;
        #pragma unroll
        for (int off = 16; off; off >>= 1) {
            s  += __shfl_xor_sync(0xffffffffu, s,  off);
            ss += __shfl_xor_sync(0xffffffffu, ss, off);
        }
        if (lane == 0) { rs[0] = s; rss[0] = ss; }
    }
    __syncthreads();
    s = rs[0]; ss = rss[0];
    mean = s * (1.0f / EMB);
    float var = fmaxf(ss - (float)EMB * mean * mean, 0.f) * (1.0f / (EMB - 1));
    inv = al[0] / (sqrtf(var) + 1e-6f);
}

template<int FP16>
__global__ void ln16_kernel(const float* __restrict__ x, uint16_t* __restrict__ y,
                            const float* __restrict__ al, const float* __restrict__ be)
{
    int row = blockIdx.x;
    float4 v = ((const float4*)(x + (size_t)row * EMB))[threadIdx.x];
    float mean, inv;
    ln_stats(v, mean, inv, al);
    float bb = be[0];
    int col = threadIdx.x * 4;
    uint16_t* rowp = y + (size_t)row * EMB;
    *(uint32_t*)(rowp + col)     = pack2<FP16>((v.x - mean) * inv + bb, (v.y - mean) * inv + bb);
    *(uint32_t*)(rowp + col + 2) = pack2<FP16>((v.z - mean) * inv + bb, (v.w - mean) * inv + bb);
}

// fused: h = x + p0 + p1 ; xh = fp16(ln2(h))
__global__ void reduce2_ln_kernel(const float* __restrict__ parts, const float* __restrict__ x,
                                  float* __restrict__ hout, uint16_t* __restrict__ yh,
                                  const float* __restrict__ al, const float* __restrict__ be)
{
    int row = blockIdx.x, col = threadIdx.x * 4;
    size_t idx = (size_t)row * EMB + col;
    float4 a  = *(const float4*)(x + idx);
    float4 p0 = *(const float4*)(parts + idx);
    float4 p1 = *(const float4*)(parts + (size_t)MROWS * EMB + idx);
    a.x += p0.x + p1.x; a.y += p0.y + p1.y; a.z += p0.z + p1.z; a.w += p0.w + p1.w;
    *(float4*)(hout + idx) = a;
    float mean, inv;
    ln_stats(a, mean, inv, al);
    float bb = be[0];
    uint16_t* rowp = yh + (size_t)row * EMB;
    *(uint32_t*)(rowp + col)     = pack2<1>((a.x - mean) * inv + bb, (a.y - mean) * inv + bb);
    *(uint32_t*)(rowp + col + 2) = pack2<1>((a.z - mean) * inv + bb, (a.w - mean) * inv + bb);
}

// ---------------- weight transposes -------------------------------------------
// merged 4x EMBxEMB transpose: z selects source, dst offset z*EMB*EMB
__global__ void wt16_x4_kernel(const float* __restrict__ w0, const float* __restrict__ w1,
                               const float* __restrict__ w2, const float* __restrict__ w3,
                               uint16_t* __restrict__ WT)
{
    const float* W = (blockIdx.z == 0) ? w0 : (blockIdx.z == 1) ? w1
                   : (blockIdx.z == 2) ? w2 : w3;
    uint16_t* dstb = WT + (size_t)blockIdx.z * EMB * EMB;
    __shared__ float t[32][132];
    int k0 = blockIdx.y * 32, n0 = blockIdx.x * 128;
    int tid = threadIdx.x;
    int lr = tid >> 5, lc = (tid & 31) * 4;
    #pragma unroll
    for (int i = 0; i < 4; i++) {
        float4 v = *(const float4*)&W[(size_t)(k0 + lr + 8*i) * EMB + n0 + lc];
        t[lr + 8*i][lc]     = v.x;
        t[lr + 8*i][lc + 1] = v.y;
        t[lr + 8*i][lc + 2] = v.z;
        t[lr + 8*i][lc + 3] = v.w;
    }
    __syncthreads();
    int n = tid >> 1, ks = (tid & 1) * 16;
    uint16_t* dst = dstb + (size_t)(n0 + n) * EMB + k0 + ks;
    #pragma unroll
    for (int j = 0; j < 8; j++) {
        int k = ks + 2*j;
        *(uint32_t*)(dst + 2*j) = pack2<0>(t[k][n], t[k + 1][n]);
    }
}

template<int FP16>
__global__ void wt16_kernel(const float* __restrict__ W, uint16_t* __restrict__ WT,
                            int K, int N)
{
    __shared__ float t[32][132];
    int k0 = blockIdx.y * 32, n0 = blockIdx.x * 128;
    int tid = threadIdx.x;
    int lr = tid >> 5, lc = (tid & 31) * 4;
    #pragma unroll
    for (int i = 0; i < 4; i++) {
        float4 v = *(const float4*)&W[(size_t)(k0 + lr + 8*i) * N + n0 + lc];
        t[lr + 8*i][lc]     = v.x;
        t[lr + 8*i][lc + 1] = v.y;
        t[lr + 8*i][lc + 2] = v.z;
        t[lr + 8*i][lc + 3] = v.w;
    }
    __syncthreads();
    int n = tid >> 1, ks = (tid & 1) * 16;
    uint16_t* dst = WT + (size_t)(n0 + n) * K + k0 + ks;
    #pragma unroll
    for (int j = 0; j < 8; j++) {
        int k = ks + 2*j;
        *(uint32_t*)(dst + 2*j) = pack2<FP16>(t[k][n], t[k + 1][n]);
    }
}

// ---------------- split-K reduce ----------------------------------------------
template<int NP>
__global__ void reduce_kernel(const float* __restrict__ parts, const float* __restrict__ res,
                              const float* __restrict__ bias, float* __restrict__ out)
{
    int row = blockIdx.x, col = threadIdx.x * 4;
    size_t idx = (size_t)row * EMB + col;
    float4 a = *(const float4*)(res + idx);
    if (bias) {
        float4 bb = *(const float4*)(bias + col);
        a.x += bb.x; a.y += bb.y; a.z += bb.z; a.w += bb.w;
    }
    #pragma unroll
    for (int p = 0; p < NP; p++) {
        float4 pv = *(const float4*)(parts + (size_t)p * MROWS * EMB + idx);
        a.x += pv.x; a.y += pv.y; a.z += pv.z; a.w += pv.w;
    }
    *(float4*)(out + idx) = a;
}

// ---------------- 16-bit mma.sync GEMM (256x128 CTA, 64x64 warp, BK=64) -------
#define ASTR 144
#define A_STAGE (256 * ASTR)
#define B_STAGE (128 * ASTR)
#define STAGE_BYTES (A_STAGE + B_STAGE)      // 55296
#define GSM_TOTAL (3 * STAGE_BYTES)          // 165888

template<int MODE, int FP16>
__global__ void __launch_bounds__(256, 1)
gemm_mma(const uint16_t* __restrict__ A3, const uint16_t* __restrict__ BT3,
         float* __restrict__ C, uint16_t* __restrict__ Cs,
         const float* __restrict__ bias, const float* __restrict__ res,
         int M, int N, int K3, int ksplit)
{
    extern __shared__ char smem[];
    uint32_t sb = smem_u32(smem);
    int tid = threadIdx.x, wid = tid >> 5, lane = tid & 31;
    int bm = blockIdx.y, bn = blockIdx.x;
    int warp_m = wid >> 1, warp_n = wid & 1;

    const int Kc = K3 / ksplit;
    const int kbase = blockIdx.z * Kc;
    const int nk = Kc / 64;

    auto load_stage = [&](int k0, int st) {
        uint32_t base = sb + st * STAGE_BYTES;
        #pragma unroll
        for (int i = 0; i < 8; i++) {
            int c = tid + i * 256;
            int row = c >> 3, kc = c & 7;
            cp16(base + row * ASTR + kc * 16,
                 A3 + (size_t)(bm * 256 + row) * K3 + k0 + kc * 8);
        }
        #pragma unroll
        for (int i = 0; i < 4; i++) {
            int c = tid + i * 256;
            int row = c >> 3, kc = c & 7;
            cp16(base + A_STAGE + row * ASTR + kc * 16,
                 BT3 + (size_t)(bn * 128 + row) * K3 + k0 + kc * 8);
        }
        cp_commit();
    };

    load_stage(kbase, 0);
    load_stage(kbase + 64, 1);

    float acc[4][8][4];
    #pragma unroll
    for (int i = 0; i < 4; i++)
        #pragma unroll
        for (int j = 0; j < 8; j++)
            #pragma unroll
            for (int r = 0; r < 4; r++) acc[i][j][r] = 0.f;

    uint32_t aBase = (uint32_t)((warp_m * 64 + (lane & 15)) * ASTR + (lane >> 4) * 16);
    uint32_t bBase = (uint32_t)(A_STAGE +
                     (warp_n * 64 + ((lane >> 4) << 3) + (lane & 7)) * ASTR +
                     ((lane >> 3) & 1) * 16);

    for (int kt = 0; kt < nk; kt++) {
        cp_wait<1>();
        __syncthreads();                         // single barrier per stage:
        int nxt = kt + 2;                        // all warps done reading buf (kt+2)%3
        if (nxt < nk) load_stage(kbase + nxt * 64, nxt % 3);

        uint32_t stb = sb + (kt % 3) * STAGE_BYTES;
        #pragma unroll
        for (int s = 0; s < 4; s++) {
            uint32_t afr[4][4], bfr[4][4];
            #pragma unroll
            for (int i = 0; i < 4; i++)
                ldsm_x4(afr[i], stb + aBase + i * 16 * ASTR + s * 32);
            #pragma unroll
            for (int ng = 0; ng < 4; ng++)
                ldsm_x4(bfr[ng], stb + bBase + ng * 16 * ASTR + s * 32);
            #pragma unroll
            for (int i = 0; i < 4; i++) {
                #pragma unroll
                for (int j = 0; j < 8; j++)
                    mma16<FP16>(acc[i][j], afr[i], &bfr[j >> 1][(j & 1) * 2]);
            }
        }
    }

    int g = lane >> 2, tig = lane & 3;
    float* Cz = (MODE == 0) ? C + (size_t)blockIdx.z * M * N : C;
    #pragma unroll
    for (int i = 0; i < 4; i++) {
        #pragma unroll
        for (int half = 0; half < 2; half++) {
            int row = bm * 256 + warp_m * 64 + i * 16 + g + half * 8;
            #pragma unroll
            for (int j = 0; j < 8; j++) {
                int col = bn * 128 + warp_n * 64 + j * 8 + tig * 2;
                float v0 = acc[i][j][half * 2];
                float v1 = acc[i][j][half * 2 + 1];
                if (MODE == 2) {
                    *(uint32_t*)(Cs + (size_t)row * N + col) = pack2<FP16>(v0, v1);
                } else if (MODE == 3) {
                    v0 = fmaxf(v0 + bias[col],     0.f);
                    v1 = fmaxf(v1 + bias[col + 1], 0.f);
                    *(uint32_t*)(Cs + (size_t)row * N + col) = pack2<FP16>(v0, v1);
                } else {
                    if (bias) { v0 += bias[col]; v1 += bias[col + 1]; }
                    size_t rb = (size_t)row * N;
                    if (res) {
                        float2 rr = *(const float2*)(res + rb + col);
                        v0 += rr.x; v1 += rr.y;
                    }
                    float2 o; o.x = v0; o.y = v1;
                    *(float2*)(Cz + rb + col) = o;
                }
            }
        }
    }
}

// ---------------- Tensor-core flash attention (256 q-rows/CTA, 32/warp) -------
#define TSTR 144
#define AQOFF 0                        // Q: 256 x 144 = 36864
#define AKOFF 36864                    // K: 2 x 64 x 144 = 18432
#define AVOFF 55296                    // V: 18432
#define AMOFF 73728                    // mask: 8192
#define ATT_SMEM 81920

__global__ void __launch_bounds__(256, 1)
attn_tc(const __nv_bfloat16* __restrict__ qkv, const int* __restrict__ mask,
        __nv_bfloat16* __restrict__ ao)
{
    extern __shared__ char smem[];
    uint32_t sb = smem_u32(smem);
    int tid = threadIdx.x, wid = tid >> 5, lane = tid & 31;
    int g = lane >> 2, tig = lane & 3;
    int bh = blockIdx.y;
    int b = bh >> 4, hd = bh & 15;
    int q0 = blockIdx.x * 256;

    const __nv_bfloat16* qg = qkv + (size_t)(b * SEQ) * QKVW + hd * DKH;

    #pragma unroll
    for (int i = 0; i < 8; i++) {
        int c = tid + i * 256;
        int row = c >> 3, kc = c & 7;
        cp16(sb + AQOFF + row * TSTR + kc * 16,
             qg + (size_t)(q0 + row) * QKVW + kc * 8);
    }
    #pragma unroll
    for (int i = 0; i < 2; i++) {
        int c = tid + i * 256;
        cp16(sb + AMOFF + c * 16, mask + (size_t)b * SEQ + c * 4);
    }
    auto load_kv = [&](int jt, int buf) {
        #pragma unroll
        for (int i = 0; i < 2; i++) {
            int c = tid + i * 256;
            int row = c >> 3, kc = c & 7;
            cp16(sb + AKOFF + buf * 9216 + row * TSTR + kc * 16,
                 qg + (size_t)(jt * 64 + row) * QKVW + EMB + kc * 8);
            cp16(sb + AVOFF + buf * 9216 + row * TSTR + kc * 16,
                 qg + (size_t)(jt * 64 + row) * QKVW + 2 * EMB + kc * 8);
        }
    };
    load_kv(0, 0);
    cp_commit();

    uint32_t qfr[2][4][4];
    float ofr[2][8][4];
    #pragma unroll
    for (int rb = 0; rb < 2; rb++)
        #pragma unroll
        for (int j = 0; j < 8; j++)
            #pragma unroll
            for (int r = 0; r < 4; r++) ofr[rb][j][r] = 0.f;
    float mm[2][2], ll[2][2];
    #pragma unroll
    for (int rb = 0; rb < 2; rb++) { mm[rb][0] = mm[rb][1] = -3.0e38f; ll[rb][0] = ll[rb][1] = 0.f; }

    uint32_t aQ0 = (uint32_t)(AQOFF + (wid * 32 + (lane & 15)) * TSTR + (lane >> 4) * 16);
    uint32_t bK  = (uint32_t)((((lane >> 4) << 3) + (lane & 7)) * TSTR + ((lane >> 3) & 1) * 16);
    uint32_t bV  = (uint32_t)((((lane >> 3) & 1) * 8 + (lane & 7)) * TSTR + (lane >> 4) * 16);

    const int NJT = SEQ / 64;
    for (int jt = 0; jt < NJT; jt++) {
        cp_wait<0>();
        __syncthreads();                          // single barrier per kv-tile
        if (jt == 0) {
            #pragma unroll
            for (int rb = 0; rb < 2; rb++)
                #pragma unroll
                for (int ks = 0; ks < 4; ks++)
                    ldsm_x4(qfr[rb][ks], sb + aQ0 + rb * 16 * TSTR + ks * 32);
        }
        if (jt + 1 < NJT) { load_kv(jt + 1, (jt + 1) & 1); cp_commit(); }

        uint32_t kb = sb + AKOFF + (jt & 1) * 9216;
        uint32_t vb = sb + AVOFF + (jt & 1) * 9216;

        float sfr[2][8][4];
        #pragma unroll
        for (int rb = 0; rb < 2; rb++)
            #pragma unroll
            for (int j = 0; j < 8; j++)
                #pragma unroll
                for (int r = 0; r < 4; r++) sfr[rb][j][r] = 0.f;
        #pragma unroll
        for (int ks = 0; ks < 4; ks++) {
            uint32_t bfr[4][4];
            #pragma unroll
            for (int ng = 0; ng < 4; ng++)
                ldsm_x4(bfr[ng], kb + bK + ng * 16 * TSTR + ks * 32);
            #pragma unroll
            for (int rb = 0; rb < 2; rb++)
                #pragma unroll
                for (int j = 0; j < 8; j++)
                    mma16<0>(sfr[rb][j], qfr[rb][ks], &bfr[j >> 1][(j & 1) * 2]);
        }

        #pragma unroll
        for (int rb = 0; rb < 2; rb++) {
            #pragma unroll
            for (int j = 0; j < 8; j++) {
                int2 mv = *(const int2*)(smem + AMOFF + (jt * 64 + j * 8 + tig * 2) * 4);
                sfr[rb][j][0] = (mv.x == 0) ? -1e30f : sfr[rb][j][0] * 0.125f;
                sfr[rb][j][1] = (mv.y == 0) ? -1e30f : sfr[rb][j][1] * 0.125f;
                sfr[rb][j][2] = (mv.x == 0) ? -1e30f : sfr[rb][j][2] * 0.125f;
                sfr[rb][j][3] = (mv.y == 0) ? -1e30f : sfr[rb][j][3] * 0.125f;
            }
            float mx0 = -3.0e38f, mx1 = -3.0e38f;
            #pragma unroll
            for (int j = 0; j < 8; j++) {
                mx0 = fmaxf(mx0, fmaxf(sfr[rb][j][0], sfr[rb][j][1]));
                mx1 = fmaxf(mx1, fmaxf(sfr[rb][j][2], sfr[rb][j][3]));
            }
            #pragma unroll
            for (int off = 1; off < 4; off <<= 1) {
                mx0 = fmaxf(mx0, __shfl_xor_sync(0xffffffffu, mx0, off));
                mx1 = fmaxf(mx1, __shfl_xor_sync(0xffffffffu, mx1, off));
            }
            float mn0 = fmaxf(mm[rb][0], mx0), mn1 = fmaxf(mm[rb][1], mx1);
            float al0 = __expf(mm[rb][0] - mn0), al1 = __expf(mm[rb][1] - mn1);
            float ls0 = 0.f, ls1 = 0.f;
            #pragma unroll
            for (int j = 0; j < 8; j++) {
                sfr[rb][j][0] = __expf(sfr[rb][j][0] - mn0);
                sfr[rb][j][1] = __expf(sfr[rb][j][1] - mn0);
                sfr[rb][j][2] = __expf(sfr[rb][j][2] - mn1);
                sfr[rb][j][3] = __expf(sfr[rb][j][3] - mn1);
                ls0 += sfr[rb][j][0] + sfr[rb][j][1];
                ls1 += sfr[rb][j][2] + sfr[rb][j][3];
            }
            #pragma unroll
            for (int off = 1; off < 4; off <<= 1) {
                ls0 += __shfl_xor_sync(0xffffffffu, ls0, off);
                ls1 += __shfl_xor_sync(0xffffffffu, ls1, off);
            }
            ll[rb][0] = ll[rb][0] * al0 + ls0;
            ll[rb][1] = ll[rb][1] * al1 + ls1;
            mm[rb][0] = mn0; mm[rb][1] = mn1;
            #pragma unroll
            for (int j = 0; j < 8; j++) {
                ofr[rb][j][0] *= al0; ofr[rb][j][1] *= al0;
                ofr[rb][j][2] *= al1; ofr[rb][j][3] *= al1;
            }
        }

        #pragma unroll
        for (int ks = 0; ks < 4; ks++) {
            uint32_t pa[2][4];
            #pragma unroll
            for (int rb = 0; rb < 2; rb++) {
                pa[rb][0] = packbf(sfr[rb][2*ks][0],   sfr[rb][2*ks][1]);
                pa[rb][1] = packbf(sfr[rb][2*ks][2],   sfr[rb][2*ks][3]);
                pa[rb][2] = packbf(sfr[rb][2*ks+1][0], sfr[rb][2*ks+1][1]);
                pa[rb][3] = packbf(sfr[rb][2*ks+1][2], sfr[rb][2*ks+1][3]);
            }
            #pragma unroll
            for (int jp = 0; jp < 4; jp++) {
                uint32_t vfr[4];
                ldsm_x4t(vfr, vb + bV + ks * 16 * TSTR + jp * 32);
                #pragma unroll
                for (int rb = 0; rb < 2; rb++) {
                    mma16<0>(ofr[rb][2*jp],     pa[rb], &vfr[0]);
                    mma16<0>(ofr[rb][2*jp + 1], pa[rb], &vfr[2]);
                }
            }
        }
    }

    #pragma unroll
    for (int rb = 0; rb < 2; rb++) {
        float inv0 = 1.f / ll[rb][0], inv1 = 1.f / ll[rb][1];
        int r0 = b * SEQ + q0 + wid * 32 + rb * 16 + g;
        #pragma unroll
        for (int half = 0; half < 2; half++) {
            int grow = r0 + half * 8;
            float inv = half ? inv1 : inv0;
            __nv_bfloat16* base = ao + (size_t)grow * EMB + hd * DKH;
            #pragma unroll
            for (int j = 0; j < 8; j++) {
                int col = j * 8 + tig * 2;
                __nv_bfloat162 hh = __floats2bfloat162_rn(ofr[rb][j][half * 2] * inv,
                                                          ofr[rb][j][half * 2 + 1] * inv);
                *(__nv_bfloat162*)(base + col) = hh;
            }
        }
    }
}

// ---------------- launch ------------------------------------------------------
extern "C" void kernel_launch(void* const* d_in, const int* in_sizes, int n_in,
                              void* d_out, int out_size)
{
    const float* x    = (const float*)d_in[0];
    const int*   mask = (const int*)  d_in[1];
    const float* wq   = (const float*)d_in[2];
    const float* wk   = (const float*)d_in[3];
    const float* wv   = (const float*)d_in[4];
    const float* wo   = (const float*)d_in[5];
    const float* ff1w = (const float*)d_in[6];
    const float* ff1b = (const float*)d_in[7];
    const float* ff2w = (const float*)d_in[8];
    const float* ff2b = (const float*)d_in[9];
    const float* ln1a = (const float*)d_in[10];
    const float* ln1b = (const float*)d_in[11];
    const float* ln2a = (const float*)d_in[12];
    const float* ln2b = (const float*)d_in[13];
    float* out = (float*)d_out;

    __nv_bfloat16 *ab, *wp, *qkvh;
    uint16_t *xh, *ffh, *wh;
    float *h, *part;
    cudaGetSymbolAddress((void**)&ab,   g_ab);
    cudaGetSymbolAddress((void**)&xh,   g_xh);
    cudaGetSymbolAddress((void**)&ffh,  g_ffh);
    cudaGetSymbolAddress((void**)&wh,   g_wh);
    cudaGetSymbolAddress((void**)&wp,   g_wp);
    cudaGetSymbolAddress((void**)&qkvh, g_qkvh);
    cudaGetSymbolAddress((void**)&h,    g_h);
    cudaGetSymbolAddress((void**)&part, g_part);
    __nv_bfloat16* wpo = wp + (size_t)(3 * EMB) * EMB;
    uint16_t* wh2 = wh + (size_t)HID * EMB;      // ff2 slot

    cudaFuncSetAttribute(attn_tc, cudaFuncAttributeMaxDynamicSharedMemorySize, ATT_SMEM);
    cudaFuncSetAttribute(gemm_mma<0,0>, cudaFuncAttributeMaxDynamicSharedMemorySize, GSM_TOTAL);
    cudaFuncSetAttribute(gemm_mma<2,0>, cudaFuncAttributeMaxDynamicSharedMemorySize, GSM_TOTAL);
    cudaFuncSetAttribute(gemm_mma<0,1>, cudaFuncAttributeMaxDynamicSharedMemorySize, GSM_TOTAL);
    cudaFuncSetAttribute(gemm_mma<3,1>, cudaFuncAttributeMaxDynamicSharedMemorySize, GSM_TOTAL);

    dim3 gQKV(QKVW / 128, MROWS / 256, 1);   // (24, 16)
    dim3 gWO (EMB / 128,  MROWS / 256, 2);   // (8, 16, 2) split-K
    dim3 gFF1(HID / 128,  MROWS / 256, 1);   // (32, 16)
    dim3 gFF2(EMB / 128,  MROWS / 256, 4);   // (8, 16, 4) split-K

    // 1) ln1(x) -> ab (bf16)
    ln16_kernel<0><<<MROWS, 256>>>(x, (uint16_t*)ab, ln1a, ln1b);
    // 2) all four EMBxEMB transposes in one launch (wq|wk|wv|wo)
    wt16_x4_kernel<<<dim3(EMB/128, EMB/32, 4), 256>>>(wq, wk, wv, wo, (uint16_t*)wp);
    // 3) ff1/ff2 fp16 transposes (independent of activations; front-loaded)
    wt16_kernel<1><<<dim3(HID/128, EMB/32), 256>>>(ff1w, wh, EMB, HID);
    wt16_kernel<1><<<dim3(EMB/128, HID/32), 256>>>(ff2w, wh2, HID, EMB);
    // 4) fused QKV projection (bf16, K=1024)
    gemm_mma<2,0><<<gQKV, 256, GSM_TOTAL>>>((const uint16_t*)ab, (const uint16_t*)wp,
                                            nullptr, (uint16_t*)qkvh, nullptr, nullptr,
                                            MROWS, QKVW, EMB, 1);
    // 5) attention -> ab (bf16, reuse), 256 q-rows per CTA
    attn_tc<<<dim3(SEQ / 256, BATCH * NH), 256, ATT_SMEM>>>(qkvh, mask, ab);
    // 6) wo partials (bf16, split-K=2)
    gemm_mma<0,0><<<gWO, 256, GSM_TOTAL>>>((const uint16_t*)ab, (const uint16_t*)wpo,
                                           part, nullptr, nullptr, nullptr,
                                           MROWS, EMB, EMB, 2);
    // 7) fused: h = x + p0 + p1 ; xh = fp16(ln2(h))
    reduce2_ln_kernel<<<MROWS, 256>>>(part, x, h, xh, ln2a, ln2b);
    // 8) ff1 = relu(xh @ ff1_w + b) in fp16, K=1024
    gemm_mma<3,1><<<gFF1, 256, GSM_TOTAL>>>(xh, wh, nullptr, ffh, ff1b, nullptr,
                                            MROWS, HID, EMB, 1);
    // 9-10) ff2 fp16 partials (split-K=4, K=4096); out = h + bias + parts
    gemm_mma<0,1><<<gFF2, 256, GSM_TOTAL>>>(ffh, wh2, part, nullptr, nullptr, nullptr,
                                            MROWS, EMB, HID, 4);
    reduce_kernel<4><<<MROWS, 256>>>(part, h, ff2b, out);
}

// round 14
// speedup vs baseline: 1.5037x; 1.5037x over previous
#include <cuda_runtime.h>
#include <cuda_bf16.h>
#include <cuda_fp16.h>
#include <math.h>
#include <stdint.h>

#define EMB 1024
#define HID 4096
#define NH 16
#define DKH 64
#define BATCH 2
#define SEQ 2048
#define MROWS (BATCH * SEQ)     // 4096
#define QKVW (3 * EMB)

// ---------------- scratch (__device__ globals, allocation-free) ---------------
__device__ __nv_bfloat16 g_ab  [MROWS * EMB];            // ln1 out, later attn out
__device__ uint16_t      g_xh  [MROWS * EMB];            // ln2 out (fp16)
__device__ uint16_t      g_ffh [(size_t)MROWS * HID];    // relu(ff1) (fp16)
__device__ uint16_t      g_wh  [(size_t)2 * HID * EMB];  // fp16 transposed ff1 | ff2
__device__ __nv_bfloat16 g_wp  [(size_t)(4 * EMB) * EMB];// plain transposed qkv|wo
__device__ __nv_bfloat16 g_qkvh[(size_t)MROWS * QKVW];   // packed q|k|v bf16
__device__ float g_h   [MROWS * EMB];
__device__ float g_part[(size_t)4 * MROWS * EMB];        // split-K partials

// ---------------- PTX helpers (base ISA only) ----------------------------------
__device__ __forceinline__ uint32_t smem_u32(const void* p) {
    return (uint32_t)__cvta_generic_to_shared(p);
}
__device__ __forceinline__ void cp16(uint32_t dst, const void* src) {
    asm volatile("cp.async.cg.shared.global [%0], [%1], 16;" :: "r"(dst), "l"(src));
}
__device__ __forceinline__ void cp_commit() {
    asm volatile("cp.async.commit_group;");
}
template<int N> __device__ __forceinline__ void cp_wait() {
    asm volatile("cp.async.wait_group %0;" :: "n"(N));
}
__device__ __forceinline__ void ldsm_x4(uint32_t* r, uint32_t addr) {
    asm volatile("ldmatrix.sync.aligned.m8n8.x4.shared.b16 {%0,%1,%2,%3}, [%4];"
                 : "=r"(r[0]), "=r"(r[1]), "=r"(r[2]), "=r"(r[3]) : "r"(addr));
}
__device__ __forceinline__ void ldsm_x4t(uint32_t* r, uint32_t addr) {
    asm volatile("ldmatrix.sync.aligned.m8n8.x4.trans.shared.b16 {%0,%1,%2,%3}, [%4];"
                 : "=r"(r[0]), "=r"(r[1]), "=r"(r[2]), "=r"(r[3]) : "r"(addr));
}
template<int FP16>
__device__ __forceinline__ void mma16(float* d, const uint32_t* a, const uint32_t* b) {
    if (FP16)
        asm volatile(
            "mma.sync.aligned.m16n8k16.row.col.f32.f16.f16.f32 "
            "{%0,%1,%2,%3}, {%4,%5,%6,%7}, {%8,%9}, {%0,%1,%2,%3};"
            : "+f"(d[0]), "+f"(d[1]), "+f"(d[2]), "+f"(d[3])
            : "r"(a[0]), "r"(a[1]), "r"(a[2]), "r"(a[3]), "r"(b[0]), "r"(b[1]));
    else
        asm volatile(
            "mma.sync.aligned.m16n8k16.row.col.f32.bf16.bf16.f32 "
            "{%0,%1,%2,%3}, {%4,%5,%6,%7}, {%8,%9}, {%0,%1,%2,%3};"
            : "+f"(d[0]), "+f"(d[1]), "+f"(d[2]), "+f"(d[3])
            : "r"(a[0]), "r"(a[1]), "r"(a[2]), "r"(a[3]), "r"(b[0]), "r"(b[1]));
}
template<int FP16>
__device__ __forceinline__ uint32_t pack2(float a, float b) {
    if (FP16) { __half2 h = __floats2half2_rn(a, b); return *(uint32_t*)&h; }
    __nv_bfloat162 h = __floats2bfloat162_rn(a, b); return *(uint32_t*)&h;
}
__device__ __forceinline__ uint32_t packbf(float a, float b) {
    __nv_bfloat162 h = __floats2bfloat162_rn(a, b);
    return *(uint32_t*)&h;
}

// ---------------- LayerNorm ----------------------------------------------------
__device__ __forceinline__ void ln_stats(float4 v, float& mean, float& inv,
                                         const float* al) {
    float s  = v.x + v.y + v.z + v.w;
    float ss = v.x*v.x + v.y*v.y + v.z*v.z + v.w*v.w;
    #pragma unroll
    for (int off = 16; off; off >>= 1) {
        s  += __shfl_xor_sync(0xffffffffu, s,  off);
        ss += __shfl_xor_sync(0xffffffffu, ss, off);
    }
    __shared__ float rs[8], rss[8];
    int warp = threadIdx.x >> 5, lane = threadIdx.x & 31;
    if (lane == 0) { rs[warp] = s; rss[warp] = ss; }
    __syncthreads();
    if (warp == 0) {
        s  = (lane < 8) ? rs[lane]  : 0.f;
        ss = (lane < 8) ? rss[lane] : 0.f;
        #pragma unroll
        for (int off = 16; off; off >>= 1) {
            s  += __shfl_xor_sync(0xffffffffu, s,  off);
            ss += __shfl_xor_sync(0xffffffffu, ss, off);
        }
        if (lane == 0) { rs[0] = s; rss[0] = ss; }
    }
    __syncthreads();
    s = rs[0]; ss = rss[0];
    mean = s * (1.0f / EMB);
    float var = fmaxf(ss - (float)EMB * mean * mean, 0.f) * (1.0f / (EMB - 1));
    inv = al[0] / (sqrtf(var) + 1e-6f);
}

template<int FP16>
__global__ void ln16_kernel(const float* __restrict__ x, uint16_t* __restrict__ y,
                            const float* __restrict__ al, const float* __restrict__ be)
{
    int row = blockIdx.x;
    float4 v = ((const float4*)(x + (size_t)row * EMB))[threadIdx.x];
    float mean, inv;
    ln_stats(v, mean, inv, al);
    float bb = be[0];
    int col = threadIdx.x * 4;
    uint16_t* rowp = y + (size_t)row * EMB;
    *(uint32_t*)(rowp + col)     = pack2<FP16>((v.x - mean) * inv + bb, (v.y - mean) * inv + bb);
    *(uint32_t*)(rowp + col + 2) = pack2<FP16>((v.z - mean) * inv + bb, (v.w - mean) * inv + bb);
}

// fused: h = x + p0 + p1 ; xh = fp16(ln2(h))
__global__ void reduce2_ln_kernel(const float* __restrict__ parts, const float* __restrict__ x,
                                  float* __restrict__ hout, uint16_t* __restrict__ yh,
                                  const float* __restrict__ al, const float* __restrict__ be)
{
    int row = blockIdx.x, col = threadIdx.x * 4;
    size_t idx = (size_t)row * EMB + col;
    float4 a  = *(const float4*)(x + idx);
    float4 p0 = *(const float4*)(parts + idx);
    float4 p1 = *(const float4*)(parts + (size_t)MROWS * EMB + idx);
    a.x += p0.x + p1.x; a.y += p0.y + p1.y; a.z += p0.z + p1.z; a.w += p0.w + p1.w;
    *(float4*)(hout + idx) = a;
    float mean, inv;
    ln_stats(a, mean, inv, al);
    float bb = be[0];
    uint16_t* rowp = yh + (size_t)row * EMB;
    *(uint32_t*)(rowp + col)     = pack2<1>((a.x - mean) * inv + bb, (a.y - mean) * inv + bb);
    *(uint32_t*)(rowp + col + 2) = pack2<1>((a.z - mean) * inv + bb, (a.w - mean) * inv + bb);
}

// ---------------- weight transposes -------------------------------------------
// merged 4x EMBxEMB transpose: z selects source, dst offset z*EMB*EMB
__global__ void wt16_x4_kernel(const float* __restrict__ w0, const float* __restrict__ w1,
                               const float* __restrict__ w2, const float* __restrict__ w3,
                               uint16_t* __restrict__ WT)
{
    const float* W = (blockIdx.z == 0) ? w0 : (blockIdx.z == 1) ? w1
                   : (blockIdx.z == 2) ? w2 : w3;
    uint16_t* dstb = WT + (size_t)blockIdx.z * EMB * EMB;
    __shared__ float t[32][132];
    int k0 = blockIdx.y * 32, n0 = blockIdx.x * 128;
    int tid = threadIdx.x;
    int lr = tid >> 5, lc = (tid & 31) * 4;
    #pragma unroll
    for (int i = 0; i < 4; i++) {
        float4 v = *(const float4*)&W[(size_t)(k0 + lr + 8*i) * EMB + n0 + lc];
        t[lr + 8*i][lc]     = v.x;
        t[lr + 8*i][lc + 1] = v.y;
        t[lr + 8*i][lc + 2] = v.z;
        t[lr + 8*i][lc + 3] = v.w;
    }
    __syncthreads();
    int n = tid >> 1, ks = (tid & 1) * 16;
    uint16_t* dst = dstb + (size_t)(n0 + n) * EMB + k0 + ks;
    #pragma unroll
    for (int j = 0; j < 8; j++) {
        int k = ks + 2*j;
        *(uint32_t*)(dst + 2*j) = pack2<0>(t[k][n], t[k + 1][n]);
    }
}

template<int FP16>
__global__ void wt16_kernel(const float* __restrict__ W, uint16_t* __restrict__ WT,
                            int K, int N)
{
    __shared__ float t[32][132];
    int k0 = blockIdx.y * 32, n0 = blockIdx.x * 128;
    int tid = threadIdx.x;
    int lr = tid >> 5, lc = (tid & 31) * 4;
    #pragma unroll
    for (int i = 0; i < 4; i++) {
        float4 v = *(const float4*)&W[(size_t)(k0 + lr + 8*i) * N + n0 + lc];
        t[lr + 8*i][lc]     = v.x;
        t[lr + 8*i][lc + 1] = v.y;
        t[lr + 8*i][lc + 2] = v.z;
        t[lr + 8*i][lc + 3] = v.w;
    }
    __syncthreads();
    int n = tid >> 1, ks = (tid & 1) * 16;
    uint16_t* dst = WT + (size_t)(n0 + n) * K + k0 + ks;
    #pragma unroll
    for (int j = 0; j < 8; j++) {
        int k = ks + 2*j;
        *(uint32_t*)(dst + 2*j) = pack2<FP16>(t[k][n], t[k + 1][n]);
    }
}

// ---------------- split-K reduce ----------------------------------------------
template<int NP>
__global__ void reduce_kernel(const float* __restrict__ parts, const float* __restrict__ res,
                              const float* __restrict__ bias, float* __restrict__ out)
{
    int row = blockIdx.x, col = threadIdx.x * 4;
    size_t idx = (size_t)row * EMB + col;
    float4 a = *(const float4*)(res + idx);
    if (bias) {
        float4 bb = *(const float4*)(bias + col);
        a.x += bb.x; a.y += bb.y; a.z += bb.z; a.w += bb.w;
    }
    #pragma unroll
    for (int p = 0; p < NP; p++) {
        float4 pv = *(const float4*)(parts + (size_t)p * MROWS * EMB + idx);
        a.x += pv.x; a.y += pv.y; a.z += pv.z; a.w += pv.w;
    }
    *(float4*)(out + idx) = a;
}

// ---------------- 16-bit mma.sync GEMM (256x128 CTA, 64x64 warp, BK=64) -------
// R11-proven two-barrier pipeline (trailing sync restored after R12 regression).
#define ASTR 144
#define A_STAGE (256 * ASTR)
#define B_STAGE (128 * ASTR)
#define STAGE_BYTES (A_STAGE + B_STAGE)      // 55296
#define GSM_TOTAL (3 * STAGE_BYTES)          // 165888

template<int MODE, int FP16>
__global__ void __launch_bounds__(256, 1)
gemm_mma(const uint16_t* __restrict__ A3, const uint16_t* __restrict__ BT3,
         float* __restrict__ C, uint16_t* __restrict__ Cs,
         const float* __restrict__ bias, const float* __restrict__ res,
         int M, int N, int K3, int ksplit)
{
    extern __shared__ char smem[];
    uint32_t sb = smem_u32(smem);
    int tid = threadIdx.x, wid = tid >> 5, lane = tid & 31;
    int bm = blockIdx.y, bn = blockIdx.x;
    int warp_m = wid >> 1, warp_n = wid & 1;

    const int Kc = K3 / ksplit;
    const int kbase = blockIdx.z * Kc;
    const int nk = Kc / 64;

    auto load_stage = [&](int k0, int st) {
        uint32_t base = sb + st * STAGE_BYTES;
        #pragma unroll
        for (int i = 0; i < 8; i++) {
            int c = tid + i * 256;
            int row = c >> 3, kc = c & 7;
            cp16(base + row * ASTR + kc * 16,
                 A3 + (size_t)(bm * 256 + row) * K3 + k0 + kc * 8);
        }
        #pragma unroll
        for (int i = 0; i < 4; i++) {
            int c = tid + i * 256;
            int row = c >> 3, kc = c & 7;
            cp16(base + A_STAGE + row * ASTR + kc * 16,
                 BT3 + (size_t)(bn * 128 + row) * K3 + k0 + kc * 8);
        }
        cp_commit();
    };

    load_stage(kbase, 0);
    load_stage(kbase + 64, 1);

    float acc[4][8][4];
    #pragma unroll
    for (int i = 0; i < 4; i++)
        #pragma unroll
        for (int j = 0; j < 8; j++)
            #pragma unroll
            for (int r = 0; r < 4; r++) acc[i][j][r] = 0.f;

    uint32_t aBase = (uint32_t)((warp_m * 64 + (lane & 15)) * ASTR + (lane >> 4) * 16);
    uint32_t bBase = (uint32_t)(A_STAGE +
                     (warp_n * 64 + ((lane >> 4) << 3) + (lane & 7)) * ASTR +
                     ((lane >> 3) & 1) * 16);

    for (int kt = 0; kt < nk; kt++) {
        cp_wait<1>();
        __syncthreads();
        int nxt = kt + 2;
        if (nxt < nk) load_stage(kbase + nxt * 64, nxt % 3);

        uint32_t stb = sb + (kt % 3) * STAGE_BYTES;
        #pragma unroll
        for (int s = 0; s < 4; s++) {
            uint32_t afr[4][4], bfr[4][4];
            #pragma unroll
            for (int i = 0; i < 4; i++)
                ldsm_x4(afr[i], stb + aBase + i * 16 * ASTR + s * 32);
            #pragma unroll
            for (int ng = 0; ng < 4; ng++)
                ldsm_x4(bfr[ng], stb + bBase + ng * 16 * ASTR + s * 32);
            #pragma unroll
            for (int i = 0; i < 4; i++) {
                #pragma unroll
                for (int j = 0; j < 8; j++)
                    mma16<FP16>(acc[i][j], afr[i], &bfr[j >> 1][(j & 1) * 2]);
            }
        }
        __syncthreads();
    }

    int g = lane >> 2, tig = lane & 3;
    float* Cz = (MODE == 0) ? C + (size_t)blockIdx.z * M * N : C;
    #pragma unroll
    for (int i = 0; i < 4; i++) {
        #pragma unroll
        for (int half = 0; half < 2; half++) {
            int row = bm * 256 + warp_m * 64 + i * 16 + g + half * 8;
            #pragma unroll
            for (int j = 0; j < 8; j++) {
                int col = bn * 128 + warp_n * 64 + j * 8 + tig * 2;
                float v0 = acc[i][j][half * 2];
                float v1 = acc[i][j][half * 2 + 1];
                if (MODE == 2) {
                    *(uint32_t*)(Cs + (size_t)row * N + col) = pack2<FP16>(v0, v1);
                } else if (MODE == 3) {
                    v0 = fmaxf(v0 + bias[col],     0.f);
                    v1 = fmaxf(v1 + bias[col + 1], 0.f);
                    *(uint32_t*)(Cs + (size_t)row * N + col) = pack2<FP16>(v0, v1);
                } else {
                    if (bias) { v0 += bias[col]; v1 += bias[col + 1]; }
                    size_t rb = (size_t)row * N;
                    if (res) {
                        float2 rr = *(const float2*)(res + rb + col);
                        v0 += rr.x; v1 += rr.y;
                    }
                    float2 o; o.x = v0; o.y = v1;
                    *(float2*)(Cz + rb + col) = o;
                }
            }
        }
    }
}

// ---------------- Tensor-core flash attention (256 q-rows/CTA, 32/warp) -------
// R11-proven two-barrier loop (trailing sync restored).
#define TSTR 144
#define AQOFF 0
#define AKOFF 36864
#define AVOFF 55296
#define AMOFF 73728
#define ATT_SMEM 81920

__global__ void __launch_bounds__(256, 1)
attn_tc(const __nv_bfloat16* __restrict__ qkv, const int* __restrict__ mask,
        __nv_bfloat16* __restrict__ ao)
{
    extern __shared__ char smem[];
    uint32_t sb = smem_u32(smem);
    int tid = threadIdx.x, wid = tid >> 5, lane = tid & 31;
    int g = lane >> 2, tig = lane & 3;
    int bh = blockIdx.y;
    int b = bh >> 4, hd = bh & 15;
    int q0 = blockIdx.x * 256;

    const __nv_bfloat16* qg = qkv + (size_t)(b * SEQ) * QKVW + hd * DKH;

    #pragma unroll
    for (int i = 0; i < 8; i++) {
        int c = tid + i * 256;
        int row = c >> 3, kc = c & 7;
        cp16(sb + AQOFF + row * TSTR + kc * 16,
             qg + (size_t)(q0 + row) * QKVW + kc * 8);
    }
    #pragma unroll
    for (int i = 0; i < 2; i++) {
        int c = tid + i * 256;
        cp16(sb + AMOFF + c * 16, mask + (size_t)b * SEQ + c * 4);
    }
    auto load_kv = [&](int jt, int buf) {
        #pragma unroll
        for (int i = 0; i < 2; i++) {
            int c = tid + i * 256;
            int row = c >> 3, kc = c & 7;
            cp16(sb + AKOFF + buf * 9216 + row * TSTR + kc * 16,
                 qg + (size_t)(jt * 64 + row) * QKVW + EMB + kc * 8);
            cp16(sb + AVOFF + buf * 9216 + row * TSTR + kc * 16,
                 qg + (size_t)(jt * 64 + row) * QKVW + 2 * EMB + kc * 8);
        }
    };
    load_kv(0, 0);
    cp_commit();

    uint32_t qfr[2][4][4];
    float ofr[2][8][4];
    #pragma unroll
    for (int rb = 0; rb < 2; rb++)
        #pragma unroll
        for (int j = 0; j < 8; j++)
            #pragma unroll
            for (int r = 0; r < 4; r++) ofr[rb][j][r] = 0.f;
    float mm[2][2], ll[2][2];
    #pragma unroll
    for (int rb = 0; rb < 2; rb++) { mm[rb][0] = mm[rb][1] = -3.0e38f; ll[rb][0] = ll[rb][1] = 0.f; }

    uint32_t aQ0 = (uint32_t)(AQOFF + (wid * 32 + (lane & 15)) * TSTR + (lane >> 4) * 16);
    uint32_t bK  = (uint32_t)((((lane >> 4) << 3) + (lane & 7)) * TSTR + ((lane >> 3) & 1) * 16);
    uint32_t bV  = (uint32_t)((((lane >> 3) & 1) * 8 + (lane & 7)) * TSTR + (lane >> 4) * 16);

    const int NJT = SEQ / 64;
    for (int jt = 0; jt < NJT; jt++) {
        cp_wait<0>();
        __syncthreads();
        if (jt == 0) {
            #pragma unroll
            for (int rb = 0; rb < 2; rb++)
                #pragma unroll
                for (int ks = 0; ks < 4; ks++)
                    ldsm_x4(qfr[rb][ks], sb + aQ0 + rb * 16 * TSTR + ks * 32);
        }
        if (jt + 1 < NJT) { load_kv(jt + 1, (jt + 1) & 1); cp_commit(); }

        uint32_t kb = sb + AKOFF + (jt & 1) * 9216;
        uint32_t vb = sb + AVOFF + (jt & 1) * 9216;

        float sfr[2][8][4];
        #pragma unroll
        for (int rb = 0; rb < 2; rb++)
            #pragma unroll
            for (int j = 0; j < 8; j++)
                #pragma unroll
                for (int r = 0; r < 4; r++) sfr[rb][j][r] = 0.f;
        #pragma unroll
        for (int ks = 0; ks < 4; ks++) {
            uint32_t bfr[4][4];
            #pragma unroll
            for (int ng = 0; ng < 4; ng++)
                ldsm_x4(bfr[ng], kb + bK + ng * 16 * TSTR + ks * 32);
            #pragma unroll
            for (int rb = 0; rb < 2; rb++)
                #pragma unroll
                for (int j = 0; j < 8; j++)
                    mma16<0>(sfr[rb][j], qfr[rb][ks], &bfr[j >> 1][(j & 1) * 2]);
        }

        #pragma unroll
        for (int rb = 0; rb < 2; rb++) {
            #pragma unroll
            for (int j = 0; j < 8; j++) {
                int2 mv = *(const int2*)(smem + AMOFF + (jt * 64 + j * 8 + tig * 2) * 4);
                sfr[rb][j][0] = (mv.x == 0) ? -1e30f : sfr[rb][j][0] * 0.125f;
                sfr[rb][j][1] = (mv.y == 0) ? -1e30f : sfr[rb][j][1] * 0.125f;
                sfr[rb][j][2] = (mv.x == 0) ? -1e30f : sfr[rb][j][2] * 0.125f;
                sfr[rb][j][3] = (mv.y == 0) ? -1e30f : sfr[rb][j][3] * 0.125f;
            }
            float mx0 = -3.0e38f, mx1 = -3.0e38f;
            #pragma unroll
            for (int j = 0; j < 8; j++) {
                mx0 = fmaxf(mx0, fmaxf(sfr[rb][j][0], sfr[rb][j][1]));
                mx1 = fmaxf(mx1, fmaxf(sfr[rb][j][2], sfr[rb][j][3]));
            }
            #pragma unroll
            for (int off = 1; off < 4; off <<= 1) {
                mx0 = fmaxf(mx0, __shfl_xor_sync(0xffffffffu, mx0, off));
                mx1 = fmaxf(mx1, __shfl_xor_sync(0xffffffffu, mx1, off));
            }
            float mn0 = fmaxf(mm[rb][0], mx0), mn1 = fmaxf(mm[rb][1], mx1);
            float al0 = __expf(mm[rb][0] - mn0), al1 = __expf(mm[rb][1] - mn1);
            float ls0 = 0.f, ls1 = 0.f;
            #pragma unroll
            for (int j = 0; j < 8; j++) {
                sfr[rb][j][0] = __expf(sfr[rb][j][0] - mn0);
                sfr[rb][j][1] = __expf(sfr[rb][j][1] - mn0);
                sfr[rb][j][2] = __expf(sfr[rb][j][2] - mn1);
                sfr[rb][j][3] = __expf(sfr[rb][j][3] - mn1);
                ls0 += sfr[rb][j][0] + sfr[rb][j][1];
                ls1 += sfr[rb][j][2] + sfr[rb][j][3];
            }
            #pragma unroll
            for (int off = 1; off < 4; off <<= 1) {
                ls0 += __shfl_xor_sync(0xffffffffu, ls0, off);
                ls1 += __shfl_xor_sync(0xffffffffu, ls1, off);
            }
            ll[rb][0] = ll[rb][0] * al0 + ls0;
            ll[rb][1] = ll[rb][1] * al1 + ls1;
            mm[rb][0] = mn0; mm[rb][1] = mn1;
            #pragma unroll
            for (int j = 0; j < 8; j++) {
                ofr[rb][j][0] *= al0; ofr[rb][j][1] *= al0;
                ofr[rb][j][2] *= al1; ofr[rb][j][3] *= al1;
            }
        }

        #pragma unroll
        for (int ks = 0; ks < 4; ks++) {
            uint32_t pa[2][4];
            #pragma unroll
            for (int rb = 0; rb < 2; rb++) {
                pa[rb][0] = packbf(sfr[rb][2*ks][0],   sfr[rb][2*ks][1]);
                pa[rb][1] = packbf(sfr[rb][2*ks][2],   sfr[rb][2*ks][3]);
                pa[rb][2] = packbf(sfr[rb][2*ks+1][0], sfr[rb][2*ks+1][1]);
                pa[rb][3] = packbf(sfr[rb][2*ks+1][2], sfr[rb][2*ks+1][3]);
            }
            #pragma unroll
            for (int jp = 0; jp < 4; jp++) {
                uint32_t vfr[4];
                ldsm_x4t(vfr, vb + bV + ks * 16 * TSTR + jp * 32);
                #pragma unroll
                for (int rb = 0; rb < 2; rb++) {
                    mma16<0>(ofr[rb][2*jp],     pa[rb], &vfr[0]);
                    mma16<0>(ofr[rb][2*jp + 1], pa[rb], &vfr[2]);
                }
            }
        }
        __syncthreads();
    }

    #pragma unroll
    for (int rb = 0; rb < 2; rb++) {
        float inv0 = 1.f / ll[rb][0], inv1 = 1.f / ll[rb][1];
        int r0 = b * SEQ + q0 + wid * 32 + rb * 16 + g;
        #pragma unroll
        for (int half = 0; half < 2; half++) {
            int grow = r0 + half * 8;
            float inv = half ? inv1 : inv0;
            __nv_bfloat16* base = ao + (size_t)grow * EMB + hd * DKH;
            #pragma unroll
            for (int j = 0; j < 8; j++) {
                int col = j * 8 + tig * 2;
                __nv_bfloat162 hh = __floats2bfloat162_rn(ofr[rb][j][half * 2] * inv,
                                                          ofr[rb][j][half * 2 + 1] * inv);
                *(__nv_bfloat162*)(base + col) = hh;
            }
        }
    }
}

// ---------------- launch ------------------------------------------------------
extern "C" void kernel_launch(void* const* d_in, const int* in_sizes, int n_in,
                              void* d_out, int out_size)
{
    const float* x    = (const float*)d_in[0];
    const int*   mask = (const int*)  d_in[1];
    const float* wq   = (const float*)d_in[2];
    const float* wk   = (const float*)d_in[3];
    const float* wv   = (const float*)d_in[4];
    const float* wo   = (const float*)d_in[5];
    const float* ff1w = (const float*)d_in[6];
    const float* ff1b = (const float*)d_in[7];
    const float* ff2w = (const float*)d_in[8];
    const float* ff2b = (const float*)d_in[9];
    const float* ln1a = (const float*)d_in[10];
    const float* ln1b = (const float*)d_in[11];
    const float* ln2a = (const float*)d_in[12];
    const float* ln2b = (const float*)d_in[13];
    float* out = (float*)d_out;

    __nv_bfloat16 *ab, *wp, *qkvh;
    uint16_t *xh, *ffh, *wh;
    float *h, *part;
    cudaGetSymbolAddress((void**)&ab,   g_ab);
    cudaGetSymbolAddress((void**)&xh,   g_xh);
    cudaGetSymbolAddress((void**)&ffh,  g_ffh);
    cudaGetSymbolAddress((void**)&wh,   g_wh);
    cudaGetSymbolAddress((void**)&wp,   g_wp);
    cudaGetSymbolAddress((void**)&qkvh, g_qkvh);
    cudaGetSymbolAddress((void**)&h,    g_h);
    cudaGetSymbolAddress((void**)&part, g_part);
    __nv_bfloat16* wpo = wp + (size_t)(3 * EMB) * EMB;
    uint16_t* wh2 = wh + (size_t)HID * EMB;      // ff2 slot

    cudaFuncSetAttribute(attn_tc, cudaFuncAttributeMaxDynamicSharedMemorySize, ATT_SMEM);
    cudaFuncSetAttribute(gemm_mma<0,0>, cudaFuncAttributeMaxDynamicSharedMemorySize, GSM_TOTAL);
    cudaFuncSetAttribute(gemm_mma<2,0>, cudaFuncAttributeMaxDynamicSharedMemorySize, GSM_TOTAL);
    cudaFuncSetAttribute(gemm_mma<0,1>, cudaFuncAttributeMaxDynamicSharedMemorySize, GSM_TOTAL);
    cudaFuncSetAttribute(gemm_mma<3,1>, cudaFuncAttributeMaxDynamicSharedMemorySize, GSM_TOTAL);

    dim3 gQKV(QKVW / 128, MROWS / 256, 1);   // (24, 16)
    dim3 gWO (EMB / 128,  MROWS / 256, 2);   // (8, 16, 2) split-K
    dim3 gFF1(HID / 128,  MROWS / 256, 1);   // (32, 16)
    dim3 gFF2(EMB / 128,  MROWS / 256, 4);   // (8, 16, 4) split-K

    // 1) ln1(x) -> ab (bf16)
    ln16_kernel<0><<<MROWS, 256>>>(x, (uint16_t*)ab, ln1a, ln1b);
    // 2) all four EMBxEMB transposes in one launch (wq|wk|wv|wo)
    wt16_x4_kernel<<<dim3(EMB/128, EMB/32, 4), 256>>>(wq, wk, wv, wo, (uint16_t*)wp);
    // 3) ff1/ff2 fp16 transposes (front-loaded, independent slots)
    wt16_kernel<1><<<dim3(HID/128, EMB/32), 256>>>(ff1w, wh, EMB, HID);
    wt16_kernel<1><<<dim3(EMB/128, HID/32), 256>>>(ff2w, wh2, HID, EMB);
    // 4) fused QKV projection (bf16, K=1024)
    gemm_mma<2,0><<<gQKV, 256, GSM_TOTAL>>>((const uint16_t*)ab, (const uint16_t*)wp,
                                            nullptr, (uint16_t*)qkvh, nullptr, nullptr,
                                            MROWS, QKVW, EMB, 1);
    // 5) attention -> ab (bf16, reuse), 256 q-rows per CTA
    attn_tc<<<dim3(SEQ / 256, BATCH * NH), 256, ATT_SMEM>>>(qkvh, mask, ab);
    // 6) wo partials (bf16, split-K=2)
    gemm_mma<0,0><<<gWO, 256, GSM_TOTAL>>>((const uint16_t*)ab, (const uint16_t*)wpo,
                                           part, nullptr, nullptr, nullptr,
                                           MROWS, EMB, EMB, 2);
    // 7) fused: h = x + p0 + p1 ; xh = fp16(ln2(h))
    reduce2_ln_kernel<<<MROWS, 256>>>(part, x, h, xh, ln2a, ln2b);
    // 8) ff1 = relu(xh @ ff1_w + b) in fp16, K=1024
    gemm_mma<3,1><<<gFF1, 256, GSM_TOTAL>>>(xh, wh, nullptr, ffh, ff1b, nullptr,
                                            MROWS, HID, EMB, 1);
    // 9-10) ff2 fp16 partials (split-K=4, K=4096); out = h + bias + parts
    gemm_mma<0,1><<<gFF2, 256, GSM_TOTAL>>>(ffh, wh2, part, nullptr, nullptr, nullptr,
                                            MROWS, EMB, HID, 4);
    reduce_kernel<4><<<MROWS, 256>>>(part, h, ff2b, out);
}